// round 10
// baseline (speedup 1.0000x reference)
#include <cuda_runtime.h>
#include <cstdint>

// Correlation cost volume via banded tf32 mma.sync, software-pipelined over
// (h, k-chunk) with cp.async double-buffered staging; 3 blocks/SM.
// out[b,d,h,w] = mean_c( x[b,c,h,w] * y[b,c,h,w-d] ), 0 where w<d (exact via
// zero-padded halo; cp.async zfill). tf32(.rna) folded into fragment loads.
// Per (b,h,wtile=128): A[i,k]=x[k,w0+i] (128x32), B[s,k]=y[k,w0-48+s] (176x32),
// P = A.B^T banded; warp m computes rows [16m,16m+16) x cols [16m,16m+64).
// K streamed in 2 chunks of 16 channels; accumulators persist across chunks.
// d = 48-(s-i); epilogue stages to St[48-d][i] so per-d gather is a contig row.
//
// R10 fix vs R9: refill of a double buffer is issued only AFTER the top-of-step
// __syncthreads, guaranteeing every reader of that buffer (two steps ago) has
// passed a barrier first. (R9 issued pre-barrier -> WAR race on kc==0 steps.)

#define BDIM 8
#define CDIM 32
#define HDIM 256
#define WDIM 512
#define MAXD 48

#define MT   128
#define NT   176
#define NTHR 256
#define HC   8                  // h rows per block
#define KC   16                 // channels per pipeline chunk
#define NSTEPS (HC * 2)

#define AP 136                  // A pitch (words), frag loads conflict-free
#define BP 184                  // B pitch (words), frag loads conflict-free
#define SP 136                  // stage pitch (words)
#define A_WORDS (KC * AP)       // 2176
#define B_WORDS (KC * BP)       // 2944
#define BUF_WORDS (A_WORDS + B_WORDS)       // 5120 (20 KB)
#define ST_OFF  (2 * BUF_WORDS)             // 10240
#define ST_WORDS ((MAXD + 1) * SP)          // 6664
#define SMEM_BYTES ((ST_OFF + ST_WORDS) * 4)  // 67616 B -> 3 blocks/SM

#define A_CHUNKS (KC * (MT / 4))   // 512 16B chunks per step
#define B_CHUNKS (KC * (NT / 4))   // 704

__device__ __forceinline__ uint32_t f2tf32(float v) {
    uint32_t r;
    asm("cvt.rna.tf32.f32 %0, %1;" : "=r"(r) : "f"(v));
    return r;
}
__device__ __forceinline__ uint32_t smem_u32(const void* p) {
    uint32_t a;
    asm("{ .reg .u64 t; cvta.to.shared.u64 t, %1; cvt.u32.u64 %0, t; }" : "=r"(a) : "l"(p));
    return a;
}
__device__ __forceinline__ void cp16(uint32_t dst, const void* src, int src_sz) {
    asm volatile("cp.async.cg.shared.global [%0], [%1], 16, %2;"
                 :: "r"(dst), "l"(src), "r"(src_sz) : "memory");
}
__device__ __forceinline__ void mma_tf32(float* c, const uint32_t* a, const uint32_t* b) {
    asm volatile(
        "mma.sync.aligned.m16n8k8.row.col.f32.tf32.tf32.f32 "
        "{%0,%1,%2,%3}, {%4,%5,%6,%7}, {%8,%9}, {%0,%1,%2,%3};"
        : "+f"(c[0]), "+f"(c[1]), "+f"(c[2]), "+f"(c[3])
        : "r"(a[0]), "r"(a[1]), "r"(a[2]), "r"(a[3]), "r"(b[0]), "r"(b[1]));
}

__global__ __launch_bounds__(NTHR, 3)
void corr_mma(const float* __restrict__ x, const float* __restrict__ y,
              float* __restrict__ out) {
    extern __shared__ float smem[];
    const uint32_t sb = smem_u32(smem);

    const int tid  = threadIdx.x;
    const int warp = tid >> 5, lane = tid & 31;
    const int w0    = blockIdx.x * MT;
    const int hbase = blockIdx.y * HC;
    const int b     = blockIdx.z;

    const size_t plane = (size_t)HDIM * WDIM;
    const float* xb = x + (size_t)b * CDIM * plane;
    const float* yb = y + (size_t)b * CDIM * plane;

    // ---- cp.async staging of one K-chunk (16 ch) of (A,B) for step s ----
    auto issue_stage = [&](int s) {
        const int hh = s >> 1, kc = s & 1, pb = s & 1;
        const float* xr = xb + (size_t)(hbase + hh) * WDIM + (size_t)(kc * KC) * plane;
        const float* yr = yb + (size_t)(hbase + hh) * WDIM + (size_t)(kc * KC) * plane;
        const uint32_t abase = sb + (pb * BUF_WORDS) * 4;
        const uint32_t bbase = abase + A_WORDS * 4;
        #pragma unroll 2
        for (int i = tid; i < A_CHUNKS + B_CHUNKS; i += NTHR) {
            if (i < A_CHUNKS) {
                const int k = i >> 5, v = (i & 31) << 2;
                cp16(abase + (k * AP + v) * 4, xr + k * plane + w0 + v, 16);
            } else {
                const int j = i - A_CHUNKS;
                const int k = j / (NT / 4), v = (j % (NT / 4)) << 2;
                const int gw = w0 - MAXD + v;
                cp16(bbase + (k * BP + v) * 4,
                     yr + k * plane + (gw >= 0 ? gw : 0), gw >= 0 ? 16 : 0);
            }
        }
    };

    // prologue: stage step 0
    issue_stage(0);
    asm volatile("cp.async.commit_group;" ::: "memory");

    const int i0 = 16 * warp;
    const int r  = lane >> 2;     // 0..7
    const int cq = lane & 3;      // 0..3
    float* St = smem + ST_OFF;

    float acc[8][4];

    for (int step = 0; step < NSTEPS; step++) {
        const int kc = step & 1;
        const int p  = step & 1;

        // wait for THIS step's buffer (the only outstanding group), then
        // barrier: separates (a) cp.async data from its readers, (b) prior
        // readers of the buffer we are about to refill from the refill.
        asm volatile("cp.async.wait_group 0;" ::: "memory");
        __syncthreads();

        // refill the other buffer for step+1; overlaps with compute below.
        if (step + 1 < NSTEPS) {
            issue_stage(step + 1);
            asm volatile("cp.async.commit_group;" ::: "memory");
        }

        if (kc == 0) {
            #pragma unroll
            for (int t = 0; t < 8; t++)
                #pragma unroll
                for (int q = 0; q < 4; q++) acc[t][q] = 0.f;
        }

        // ---- banded MMA on chunk p (16 channels = 2 k-steps of 8) ----
        const float* As = smem + p * BUF_WORDS;   // [KC][AP] fp32
        const float* Bs = As + A_WORDS;           // [KC][BP] fp32

        #pragma unroll
        for (int ks = 0; ks < 2; ks++) {
            const int k0 = 8 * ks;
            uint32_t a[4];
            a[0] = f2tf32(As[(k0 + cq)     * AP + i0 + r]);
            a[1] = f2tf32(As[(k0 + cq)     * AP + i0 + r + 8]);
            a[2] = f2tf32(As[(k0 + cq + 4) * AP + i0 + r]);
            a[3] = f2tf32(As[(k0 + cq + 4) * AP + i0 + r + 8]);
            #pragma unroll
            for (int t = 0; t < 8; t++) {
                const int s0 = i0 + 8 * t;
                uint32_t bfr[2];
                bfr[0] = f2tf32(Bs[(k0 + cq)     * BP + s0 + r]);
                bfr[1] = f2tf32(Bs[(k0 + cq + 4) * BP + s0 + r]);
                mma_tf32(acc[t], a, bfr);
            }
        }

        if (kc == 1) {
            // ---- scatter into shift-normalized stage St[u = 48-d][i] ----
            // St WAR vs previous gather: the two top-of-step barriers since the
            // previous gather order those reads before these writes.
            #pragma unroll
            for (int t = 0; t < 8; t++) {
                #pragma unroll
                for (int q = 0; q < 4; q++) {
                    const int re = r + (q >= 2 ? 8 : 0);
                    const int sl = 8 * t + 2 * cq + (q & 1);
                    const int u  = sl - re;
                    if (u >= 1 && u <= MAXD)
                        St[u * SP + i0 + re] = acc[t][q];
                }
            }
            __syncthreads();

            // ---- gather row u = 48-d (contiguous) + coalesced STG.128 ----
            const int h = hbase + (step >> 1);
            const float scale = 1.0f / (float)CDIM;
            const int iq = 4 * lane;
            #pragma unroll
            for (int k = 0; k < 6; k++) {
                const int d = warp + 8 * k;
                float4 v = *reinterpret_cast<const float4*>(&St[(MAXD - d) * SP + iq]);
                v.x *= scale; v.y *= scale; v.z *= scale; v.w *= scale;
                *reinterpret_cast<float4*>(
                    out + (((size_t)b * MAXD + d) * HDIM + h) * WDIM + w0 + iq) = v;
            }
        }
    }
}

extern "C" void kernel_launch(void* const* d_in, const int* in_sizes, int n_in,
                              void* d_out, int out_size) {
    const float* x = (const float*)d_in[0];
    const float* y = (const float*)d_in[1];
    float* out = (float*)d_out;

    cudaFuncSetAttribute(corr_mma,
                         cudaFuncAttributeMaxDynamicSharedMemorySize, SMEM_BYTES);

    dim3 grid(WDIM / MT, HDIM / HC, BDIM);   // (4, 32, 8) = 1024 blocks
    corr_mma<<<grid, NTHR, SMEM_BYTES>>>(x, y, out);
}

// round 11
// speedup vs baseline: 1.0667x; 1.0667x over previous
#include <cuda_runtime.h>
#include <cstdint>

// Correlation cost volume via banded tf32 mma.sync, software-pipelined over
// (h, k-chunk) with cp.async double-buffered staging; 3 blocks/SM.
// out[b,d,h,w] = mean_c( x[b,c,h,w] * y[b,c,h,w-d] ), 0 where w<d (exact via
// zero-padded halo; cp.async zfill). tf32(.rna) folded into fragment loads.
// Per (b,h,wtile=128): A[i,k]=x[k,w0+i] (128x32), B[s,k]=y[k,w0-48+s] (176x32),
// P = A.B^T banded; warp m computes rows [16m,16m+16) x cols [16m,16m+64).
// K streamed in 2 chunks of 16 channels; accumulators persist across chunks.
// d = 48-(s-i); epilogue stages to St[48-d][i] so per-d gather is a contig row.
//
// R11: depth-2 pipeline (issue s+1, wait_group 1 -> copy hides behind a FULL
// step) + every step ends with a __syncthreads so the refill of a buffer is
// always barrier-separated from its readers two steps earlier (R9's race,
// R10's serialization both avoided).

#define BDIM 8
#define CDIM 32
#define HDIM 256
#define WDIM 512
#define MAXD 48

#define MT   128
#define NT   176
#define NTHR 256
#define HC   8                  // h rows per block
#define KC   16                 // channels per pipeline chunk
#define NSTEPS (HC * 2)

#define AP 136                  // A pitch (words), frag loads conflict-free
#define BP 184                  // B pitch (words), frag loads conflict-free
#define SP 136                  // stage pitch (words)
#define A_WORDS (KC * AP)       // 2176
#define B_WORDS (KC * BP)       // 2944
#define BUF_WORDS (A_WORDS + B_WORDS)       // 5120 (20 KB)
#define ST_OFF  (2 * BUF_WORDS)             // 10240
#define ST_WORDS ((MAXD + 1) * SP)          // 6664
#define SMEM_BYTES ((ST_OFF + ST_WORDS) * 4)  // 67616 B -> 3 blocks/SM

#define A_CHUNKS (KC * (MT / 4))   // 512 16B chunks per step
#define B_CHUNKS (KC * (NT / 4))   // 704

__device__ __forceinline__ uint32_t f2tf32(float v) {
    uint32_t r;
    asm("cvt.rna.tf32.f32 %0, %1;" : "=r"(r) : "f"(v));
    return r;
}
__device__ __forceinline__ uint32_t smem_u32(const void* p) {
    uint32_t a;
    asm("{ .reg .u64 t; cvta.to.shared.u64 t, %1; cvt.u32.u64 %0, t; }" : "=r"(a) : "l"(p));
    return a;
}
__device__ __forceinline__ void cp16(uint32_t dst, const void* src, int src_sz) {
    asm volatile("cp.async.cg.shared.global [%0], [%1], 16, %2;"
                 :: "r"(dst), "l"(src), "r"(src_sz) : "memory");
}
__device__ __forceinline__ void mma_tf32(float* c, const uint32_t* a, const uint32_t* b) {
    asm volatile(
        "mma.sync.aligned.m16n8k8.row.col.f32.tf32.tf32.f32 "
        "{%0,%1,%2,%3}, {%4,%5,%6,%7}, {%8,%9}, {%0,%1,%2,%3};"
        : "+f"(c[0]), "+f"(c[1]), "+f"(c[2]), "+f"(c[3])
        : "r"(a[0]), "r"(a[1]), "r"(a[2]), "r"(a[3]), "r"(b[0]), "r"(b[1]));
}

__global__ __launch_bounds__(NTHR, 3)
void corr_mma(const float* __restrict__ x, const float* __restrict__ y,
              float* __restrict__ out) {
    extern __shared__ float smem[];
    const uint32_t sb = smem_u32(smem);

    const int tid  = threadIdx.x;
    const int warp = tid >> 5, lane = tid & 31;
    const int w0    = blockIdx.x * MT;
    const int hbase = blockIdx.y * HC;
    const int b     = blockIdx.z;

    const size_t plane = (size_t)HDIM * WDIM;
    const float* xb = x + (size_t)b * CDIM * plane;
    const float* yb = y + (size_t)b * CDIM * plane;

    // ---- cp.async staging of one K-chunk (16 ch) of (A,B) for step s ----
    auto issue_stage = [&](int s) {
        const int hh = s >> 1, kc = s & 1, pb = s & 1;
        const float* xr = xb + (size_t)(hbase + hh) * WDIM + (size_t)(kc * KC) * plane;
        const float* yr = yb + (size_t)(hbase + hh) * WDIM + (size_t)(kc * KC) * plane;
        const uint32_t abase = sb + (pb * BUF_WORDS) * 4;
        const uint32_t bbase = abase + A_WORDS * 4;
        #pragma unroll 2
        for (int i = tid; i < A_CHUNKS + B_CHUNKS; i += NTHR) {
            if (i < A_CHUNKS) {
                const int k = i >> 5, v = (i & 31) << 2;
                cp16(abase + (k * AP + v) * 4, xr + k * plane + w0 + v, 16);
            } else {
                const int j = i - A_CHUNKS;
                const int k = j / (NT / 4), v = (j % (NT / 4)) << 2;
                const int gw = w0 - MAXD + v;
                cp16(bbase + (k * BP + v) * 4,
                     yr + k * plane + (gw >= 0 ? gw : 0), gw >= 0 ? 16 : 0);
            }
        }
    };

    // prologue: stage step 0
    issue_stage(0);
    asm volatile("cp.async.commit_group;" ::: "memory");

    const int i0 = 16 * warp;
    const int r  = lane >> 2;     // 0..7
    const int cq = lane & 3;      // 0..3
    float* St = smem + ST_OFF;

    float acc[8][4];

    for (int step = 0; step < NSTEPS; step++) {
        const int kc = step & 1;
        const int p  = step & 1;

        // Issue next step's copy FIRST (depth-2: it overlaps this whole step).
        // Safe: the buffer it writes was last read in step-1's MMA, and every
        // step ends with a __syncthreads (below), so a barrier separates those
        // reads from this refill.
        if (step + 1 < NSTEPS) {
            issue_stage(step + 1);
            asm volatile("cp.async.commit_group;" ::: "memory");
            asm volatile("cp.async.wait_group 1;" ::: "memory");
        } else {
            asm volatile("cp.async.wait_group 0;" ::: "memory");
        }
        __syncthreads();   // buffer p's data visible to all threads

        if (kc == 0) {
            #pragma unroll
            for (int t = 0; t < 8; t++)
                #pragma unroll
                for (int q = 0; q < 4; q++) acc[t][q] = 0.f;
        }

        // ---- banded MMA on chunk p (16 channels = 2 k-steps of 8) ----
        const float* As = smem + p * BUF_WORDS;   // [KC][AP] fp32
        const float* Bs = As + A_WORDS;           // [KC][BP] fp32

        #pragma unroll
        for (int ks = 0; ks < 2; ks++) {
            const int k0 = 8 * ks;
            uint32_t a[4];
            a[0] = f2tf32(As[(k0 + cq)     * AP + i0 + r]);
            a[1] = f2tf32(As[(k0 + cq)     * AP + i0 + r + 8]);
            a[2] = f2tf32(As[(k0 + cq + 4) * AP + i0 + r]);
            a[3] = f2tf32(As[(k0 + cq + 4) * AP + i0 + r + 8]);
            #pragma unroll
            for (int t = 0; t < 8; t++) {
                const int s0 = i0 + 8 * t;
                uint32_t bfr[2];
                bfr[0] = f2tf32(Bs[(k0 + cq)     * BP + s0 + r]);
                bfr[1] = f2tf32(Bs[(k0 + cq + 4) * BP + s0 + r]);
                mma_tf32(acc[t], a, bfr);
            }
        }

        if (kc == 0) {
            __syncthreads();   // end-of-step barrier: orders these MMA reads
                               // before the refill issued at step+2's top
        } else {
            // ---- scatter into shift-normalized stage St[u = 48-d][i] ----
            #pragma unroll
            for (int t = 0; t < 8; t++) {
                #pragma unroll
                for (int q = 0; q < 4; q++) {
                    const int re = r + (q >= 2 ? 8 : 0);
                    const int sl = 8 * t + 2 * cq + (q & 1);
                    const int u  = sl - re;
                    if (u >= 1 && u <= MAXD)
                        St[u * SP + i0 + re] = acc[t][q];
                }
            }
            __syncthreads();   // doubles as end-of-step barrier

            // ---- gather row u = 48-d (contiguous) + coalesced STG.128 ----
            const int h = hbase + (step >> 1);
            const float scale = 1.0f / (float)CDIM;
            const int iq = 4 * lane;
            #pragma unroll
            for (int k = 0; k < 6; k++) {
                const int d = warp + 8 * k;
                float4 v = *reinterpret_cast<const float4*>(&St[(MAXD - d) * SP + iq]);
                v.x *= scale; v.y *= scale; v.z *= scale; v.w *= scale;
                *reinterpret_cast<float4*>(
                    out + (((size_t)b * MAXD + d) * HDIM + h) * WDIM + w0 + iq) = v;
            }
            // St WAR vs next scatter: next scatter is 2 steps away, separated
            // by that path's top-of-step and end-of-step barriers.
        }
    }
}

extern "C" void kernel_launch(void* const* d_in, const int* in_sizes, int n_in,
                              void* d_out, int out_size) {
    const float* x = (const float*)d_in[0];
    const float* y = (const float*)d_in[1];
    float* out = (float*)d_out;

    cudaFuncSetAttribute(corr_mma,
                         cudaFuncAttributeMaxDynamicSharedMemorySize, SMEM_BYTES);

    dim3 grid(WDIM / MT, HDIM / HC, BDIM);   // (4, 32, 8) = 1024 blocks
    corr_mma<<<grid, NTHR, SMEM_BYTES>>>(x, y, out);
}